// round 6
// baseline (speedup 1.0000x reference)
#include <cuda_runtime.h>
#include <math.h>

#define N 2048
#define F 64
#define H 128
#define C 2
#define NEG 0.01f
#define EPS 1e-5f
// E = N*(N-1)/2
#define E_EDGES 2096128

// ---------------- scratch (static device globals; no allocation) ----------------
__device__ float g_P1[N * H];
__device__ float g_P2[N * H];
__device__ float g_H3[N * F];
// 6 accumulator segments (sum1,sq1,sum2,sq2,sum5,sq5), each H entries strided by
// 128 floats (512B) to spread atomics across L2 slices.
__device__ float g_acc[6 * H * 128];
__device__ float g_s1[H], g_t1[H], g_s2[H], g_t2[H];
__device__ __align__(16) float g_v[H];
__device__ float g_c0[1];
// z storage: E * H fp32 = 1.073 GB
__device__ float g_Z[(size_t)E_EDGES * H];

// ---------------- init: zero accumulators + output diagonal ----------------
__global__ void k_init(float* __restrict__ O) {
    int t = blockIdx.x * 256 + threadIdx.x;   // 0..2047
    if (t < 6 * H) g_acc[t * 128] = 0.0f;     // (seg*H + k)*128
    if (t < N) {
        size_t d = ((size_t)t * N + t) * C;
        O[d] = 0.0f;
        O[d + 1] = 0.0f;
    }
}

// ---------------- node layer 1: P1 = leaky(nf@W1+b1), accumulate stats ----------------
__global__ void k_node1(const float* __restrict__ nf, const float* __restrict__ W1,
                        const float* __restrict__ b1) {
    int gid = blockIdx.x * 256 + threadIdx.x;   // N*H
    int r = gid >> 7, k = gid & 127;
    float acc = b1[k];
    const float* nr = nf + r * F;
#pragma unroll 8
    for (int f = 0; f < F; f++) acc = fmaf(nr[f], W1[f * H + k], acc);
    float z = acc > 0.0f ? acc : NEG * acc;
    g_P1[gid] = z;
    atomicAdd(&g_acc[0 * H * 128 + k * 128], z);
    atomicAdd(&g_acc[1 * H * 128 + k * 128], z * z);
}

__global__ void k_stats1(const float* __restrict__ g, const float* __restrict__ be) {
    int k = threadIdx.x;
    float sum = g_acc[0 * H * 128 + k * 128];
    float sq  = g_acc[1 * H * 128 + k * 128];
    float m = sum * (1.0f / N);
    float var = sq * (1.0f / N) - m * m;
    float s = g[k] / sqrtf(var + EPS);
    g_s1[k] = s;
    g_t1[k] = be[k] - m * s;
}

// ---------------- node layer 2 ----------------
__global__ void k_node2(const float* __restrict__ W2, const float* __restrict__ b2) {
    __shared__ float ss[H], st[H];
    int tid = threadIdx.x;
    if (tid < H) { ss[tid] = g_s1[tid]; st[tid] = g_t1[tid]; }
    __syncthreads();
    int gid = blockIdx.x * 256 + tid;   // N*H
    int r = gid >> 7, k = gid & 127;
    float acc = b2[k];
    const float* pr = g_P1 + r * H;
#pragma unroll 8
    for (int f = 0; f < H; f++)
        acc = fmaf(fmaf(pr[f], ss[f], st[f]), W2[f * H + k], acc);
    float z = acc > 0.0f ? acc : NEG * acc;
    g_P2[gid] = z;
    atomicAdd(&g_acc[2 * H * 128 + k * 128], z);
    atomicAdd(&g_acc[3 * H * 128 + k * 128], z * z);
}

__global__ void k_stats2(const float* __restrict__ g, const float* __restrict__ be) {
    int k = threadIdx.x;
    float sum = g_acc[2 * H * 128 + k * 128];
    float sq  = g_acc[3 * H * 128 + k * 128];
    float m = sum * (1.0f / N);
    float var = sq * (1.0f / N) - m * m;
    float s = g[k] / sqrtf(var + EPS);
    g_s2[k] = s;
    g_t2[k] = be[k] - m * s;
}

// ---------------- node layer 3: H3 = BN2(P2)@W3 + b3 + nf ----------------
__global__ void k_node3(const float* __restrict__ nf, const float* __restrict__ W3,
                        const float* __restrict__ b3) {
    __shared__ float ss[H], st[H];
    int tid = threadIdx.x;
    if (tid < H) { ss[tid] = g_s2[tid]; st[tid] = g_t2[tid]; }
    __syncthreads();
    int gid = blockIdx.x * 256 + tid;   // N*F
    int r = gid >> 6, f = gid & 63;
    float acc = b3[f] + nf[gid];
    const float* pr = g_P2 + r * H;
#pragma unroll 8
    for (int kk = 0; kk < H; kk++)
        acc = fmaf(fmaf(pr[kk], ss[kk], st[kk]), W3[kk * F + f], acc);
    g_H3[gid] = acc;
}

// ---------------- edge pass 1: z = leaky((h_i . h_j) @ W5 + b5), store + stats ----------------
// Block = (j-chunk of 128, node i). GEMM: h_j[128x64] @ (diag(h_i)*W5)[64x128].
// 256 threads, 8x8 register tile per thread.
__global__ void __launch_bounds__(256, 2)
k_edge1(const float* __restrict__ W5, const float* __restrict__ b5) {
    int i = blockIdx.y;
    int j0 = blockIdx.x << 7;
    if (j0 + 127 <= i) return;   // chunk entirely at/below diagonal

    extern __shared__ float sm[];
    float* sW = sm;                  // [64][128]  diag(h_i)*W5
    float* sH = sm + 64 * 128;       // [128][64]  h_j tile
    float* sR = sm + 64 * 128 + 128 * 64;  // [16][128] sum + [16][128] sumsq

    int tid = threadIdx.x;
    const float* hi = g_H3 + (size_t)i * F;

#pragma unroll
    for (int t = 0; t < 32; t++) {
        int idx = tid + 256 * t;             // 8192 = 64*128
        int f = idx >> 7;
        sW[idx] = hi[f] * W5[idx];           // W5 row-major [f*H + k]
    }
#pragma unroll
    for (int t = 0; t < 32; t++) {
        int idx = tid + 256 * t;             // 8192 = 128*64
        int j = idx >> 6, f = idx & 63;
        int jg = j0 + j;
        sH[idx] = (jg > i) ? g_H3[(size_t)jg * F + f] : 0.0f;
    }
    __syncthreads();

    int tx = tid & 15, ty = tid >> 4;
    float acc[8][8];
#pragma unroll
    for (int a = 0; a < 8; a++)
#pragma unroll
        for (int b = 0; b < 8; b++) acc[a][b] = 0.0f;

#pragma unroll 4
    for (int f = 0; f < F; f++) {
        float av[8], bv[8];
#pragma unroll
        for (int u = 0; u < 8; u++) av[u] = sH[(ty + 16 * u) * 64 + f];
#pragma unroll
        for (int u = 0; u < 8; u++) bv[u] = sW[f * 128 + tx + 16 * u];
#pragma unroll
        for (int uj = 0; uj < 8; uj++)
#pragma unroll
            for (int uk = 0; uk < 8; uk++)
                acc[uj][uk] = fmaf(av[uj], bv[uk], acc[uj][uk]);
    }

    float bk[8];
#pragma unroll
    for (int u = 0; u < 8; u++) bk[u] = b5[tx + 16 * u];

    float ps[8], pq[8];
#pragma unroll
    for (int u = 0; u < 8; u++) { ps[u] = 0.0f; pq[u] = 0.0f; }

    size_t zbase_i = ((size_t)i * (2 * N - i - 1)) >> 1;   // triangular row offset
#pragma unroll
    for (int uj = 0; uj < 8; uj++) {
        int j = j0 + ty + 16 * uj;
        if (j > i) {
            size_t zb = (zbase_i + (size_t)(j - i - 1)) << 7;   // *H
#pragma unroll
            for (int uk = 0; uk < 8; uk++) {
                float z = acc[uj][uk] + bk[uk];
                z = z > 0.0f ? z : NEG * z;
                g_Z[zb + tx + 16 * uk] = z;
                ps[uk] += z;
                pq[uk] += z * z;
            }
        }
    }

    // block-level column reduction, then one global atomic per column
#pragma unroll
    for (int uk = 0; uk < 8; uk++) {
        int k = tx + 16 * uk;
        sR[ty * 128 + k] = ps[uk];
        sR[2048 + ty * 128 + k] = pq[uk];
    }
    __syncthreads();
    if (tid < 128) {
        float s = 0.0f;
#pragma unroll
        for (int t = 0; t < 16; t++) s += sR[t * 128 + tid];
        atomicAdd(&g_acc[4 * H * 128 + tid * 128], s);
    } else {
        int k = tid - 128;
        float s = 0.0f;
#pragma unroll
        for (int t = 0; t < 16; t++) s += sR[2048 + t * 128 + k];
        atomicAdd(&g_acc[5 * H * 128 + k * 128], s);
    }
}

// ---------------- edge stats: fold BN affine + W6 into v[k], c0 ----------------
__global__ void k_estats(const float* __restrict__ g5, const float* __restrict__ be5,
                         const float* __restrict__ W6, const float* __restrict__ b6) {
    __shared__ float red[H];
    int k = threadIdx.x;
    double cnt = (double)E_EDGES;
    float sum = g_acc[4 * H * 128 + k * 128];
    float sq  = g_acc[5 * H * 128 + k * 128];
    float m = (float)((double)sum / cnt);
    float var = (float)((double)sq / cnt) - m * m;
    float s = g5[k] / sqrtf(var + EPS);
    float t = be5[k] - m * s;
    float dw = W6[k * 2 + 1] - W6[k * 2 + 0];
    g_v[k] = s * dw;
    red[k] = t * dw;
    __syncthreads();
    for (int off = 64; off > 0; off >>= 1) {
        if (k < off) red[k] += red[k + off];
        __syncthreads();
    }
    if (k == 0) g_c0[0] = red[0] + (b6[1] - b6[0]);
}

// ---------------- edge pass 2: sigmoid(z.v + c0) -> symmetric scatter ----------------
// Warp per edge: fully coalesced 512B z-row read.
__global__ void k_edge2(float* __restrict__ O) {
    int i = blockIdx.y;
    int j0 = blockIdx.x << 7;
    if (j0 + 127 <= i) return;
    int lane = threadIdx.x & 31, w = threadIdx.x >> 5;
    float4 vv = *((const float4*)g_v + lane);
    float c0 = g_c0[0];
    size_t zbase_i = ((size_t)i * (2 * N - i - 1)) >> 1;
    float2* O2 = (float2*)O;

    for (int jj = w; jj < 128; jj += 8) {
        int j = j0 + jj;
        if (j <= i) continue;
        size_t zb = (zbase_i + (size_t)(j - i - 1)) << 7;
        float4 z4 = *((const float4*)(g_Z + zb) + lane);
        float d = z4.x * vv.x + z4.y * vv.y + z4.z * vv.z + z4.w * vv.w;
#pragma unroll
        for (int off = 16; off; off >>= 1) d += __shfl_xor_sync(0xffffffffu, d, off);
        if (lane == 0) {
            d += c0;
            float p1 = 1.0f / (1.0f + expf(-d));   // softmax over 2 classes
            float p0 = 1.0f - p1;
            float2 pr = make_float2(p0, p1);
            O2[(size_t)i * N + j] = pr;
            O2[(size_t)j * N + i] = pr;
        }
    }
}

// ---------------- launch ----------------
extern "C" void kernel_launch(void* const* d_in, const int* in_sizes, int n_in,
                              void* d_out, int out_size) {
    // metadata order: x, node_features, W1,b1,g1,be1, W2,b2,g2,be2, W3,b3, W5,b5,g5,be5, W6,b6
    const float* nf  = (const float*)d_in[1];
    const float* W1  = (const float*)d_in[2];
    const float* b1  = (const float*)d_in[3];
    const float* g1  = (const float*)d_in[4];
    const float* be1 = (const float*)d_in[5];
    const float* W2  = (const float*)d_in[6];
    const float* b2  = (const float*)d_in[7];
    const float* g2  = (const float*)d_in[8];
    const float* be2 = (const float*)d_in[9];
    const float* W3  = (const float*)d_in[10];
    const float* b3  = (const float*)d_in[11];
    const float* W5  = (const float*)d_in[12];
    const float* b5  = (const float*)d_in[13];
    const float* g5  = (const float*)d_in[14];
    const float* be5 = (const float*)d_in[15];
    const float* W6  = (const float*)d_in[16];
    const float* b6  = (const float*)d_in[17];
    float* O = (float*)d_out;

    cudaFuncSetAttribute(k_edge1, cudaFuncAttributeMaxDynamicSharedMemorySize, 81920);

    k_init<<<8, 256>>>(O);
    k_node1<<<(N * H) / 256, 256>>>(nf, W1, b1);
    k_stats1<<<1, H>>>(g1, be1);
    k_node2<<<(N * H) / 256, 256>>>(W2, b2);
    k_stats2<<<1, H>>>(g2, be2);
    k_node3<<<(N * F) / 256, 256>>>(nf, W3, b3);

    dim3 egrid(N / 128, N);
    k_edge1<<<egrid, 256, 81920>>>(W5, b5);
    k_estats<<<1, H>>>(g5, be5, W6, b6);
    k_edge2<<<egrid, 256>>>(O);
}

// round 12
// speedup vs baseline: 1.7179x; 1.7179x over previous
#include <cuda_runtime.h>
#include <cstdint>
#include <math.h>

#define N 2048
#define F 64
#define H 128
#define C 2
#define NEG 0.01f
#define EPS 1e-5f
#define E_EDGES 2096128

// ---------------- scratch (static device globals) ----------------
__device__ float g_P1[N * H];
__device__ float g_P2[N * H];
__device__ __align__(16) float g_H3[N * F];
__device__ float g_acc[6 * H * 128];
__device__ float g_s1[H], g_t1[H], g_s2[H], g_t2[H];
__device__ __align__(16) float g_v[H];
__device__ float g_c0[1];

// ---------------- helpers ----------------
__device__ __forceinline__ float tf32r(float x) {
    float y;
    asm("cvt.rna.tf32.f32 %0, %1;" : "=f"(y) : "f"(x));
    return y;
}
__device__ __forceinline__ void mma8(float* c, const uint32_t* a, const uint32_t* b) {
    asm volatile(
        "mma.sync.aligned.m16n8k8.row.col.f32.tf32.tf32.f32 "
        "{%0,%1,%2,%3}, {%4,%5,%6,%7}, {%8,%9}, {%0,%1,%2,%3};"
        : "+f"(c[0]), "+f"(c[1]), "+f"(c[2]), "+f"(c[3])
        : "r"(a[0]), "r"(a[1]), "r"(a[2]), "r"(a[3]), "r"(b[0]), "r"(b[1]));
}

// ---------------- init: zero accumulators + output diagonal ----------------
__global__ void k_init(float* __restrict__ O) {
    int t = blockIdx.x * 256 + threadIdx.x;
    if (t < 6 * H) g_acc[t * 128] = 0.0f;
    if (t < N) {
        size_t d = ((size_t)t * N + t) * C;
        O[d] = 0.0f;
        O[d + 1] = 0.0f;
    }
}

// ---------------- node layers (4-way ILP) ----------------
__global__ void k_node1(const float* __restrict__ nf, const float* __restrict__ W1,
                        const float* __restrict__ b1) {
    int gid = blockIdx.x * 256 + threadIdx.x;   // N*H/4 threads
    int r = gid >> 5, kb = gid & 31;
    float acc[4];
#pragma unroll
    for (int c = 0; c < 4; c++) acc[c] = b1[kb + 32 * c];
    const float* nr = nf + r * F;
#pragma unroll 8
    for (int f = 0; f < F; f++) {
        float x = nr[f];
        const float* w = W1 + f * H + kb;
#pragma unroll
        for (int c = 0; c < 4; c++) acc[c] = fmaf(x, w[32 * c], acc[c]);
    }
#pragma unroll
    for (int c = 0; c < 4; c++) {
        int k = kb + 32 * c;
        float z = acc[c] > 0.0f ? acc[c] : NEG * acc[c];
        g_P1[r * H + k] = z;
        atomicAdd(&g_acc[0 * H * 128 + k * 128], z);
        atomicAdd(&g_acc[1 * H * 128 + k * 128], z * z);
    }
}
__global__ void k_stats1(const float* __restrict__ g, const float* __restrict__ be) {
    int k = threadIdx.x;
    float m = g_acc[0 * H * 128 + k * 128] * (1.0f / N);
    float var = g_acc[1 * H * 128 + k * 128] * (1.0f / N) - m * m;
    float s = g[k] / sqrtf(var + EPS);
    g_s1[k] = s;
    g_t1[k] = be[k] - m * s;
}
__global__ void k_node2(const float* __restrict__ W2, const float* __restrict__ b2) {
    __shared__ float ss[H], st[H];
    int tid = threadIdx.x;
    if (tid < H) { ss[tid] = g_s1[tid]; st[tid] = g_t1[tid]; }
    __syncthreads();
    int gid = blockIdx.x * 256 + tid;
    int r = gid >> 5, kb = gid & 31;
    float acc[4];
#pragma unroll
    for (int c = 0; c < 4; c++) acc[c] = b2[kb + 32 * c];
    const float* pr = g_P1 + r * H;
#pragma unroll 8
    for (int f = 0; f < H; f++) {
        float x = fmaf(pr[f], ss[f], st[f]);
        const float* w = W2 + f * H + kb;
#pragma unroll
        for (int c = 0; c < 4; c++) acc[c] = fmaf(x, w[32 * c], acc[c]);
    }
#pragma unroll
    for (int c = 0; c < 4; c++) {
        int k = kb + 32 * c;
        float z = acc[c] > 0.0f ? acc[c] : NEG * acc[c];
        g_P2[r * H + k] = z;
        atomicAdd(&g_acc[2 * H * 128 + k * 128], z);
        atomicAdd(&g_acc[3 * H * 128 + k * 128], z * z);
    }
}
__global__ void k_stats2(const float* __restrict__ g, const float* __restrict__ be) {
    int k = threadIdx.x;
    float m = g_acc[2 * H * 128 + k * 128] * (1.0f / N);
    float var = g_acc[3 * H * 128 + k * 128] * (1.0f / N) - m * m;
    float s = g[k] / sqrtf(var + EPS);
    g_s2[k] = s;
    g_t2[k] = be[k] - m * s;
}
__global__ void k_node3(const float* __restrict__ nf, const float* __restrict__ W3,
                        const float* __restrict__ b3) {
    __shared__ float ss[H], st[H];
    int tid = threadIdx.x;
    if (tid < H) { ss[tid] = g_s2[tid]; st[tid] = g_t2[tid]; }
    __syncthreads();
    int gid = blockIdx.x * 256 + tid;   // N*F/4 threads
    int r = gid >> 4, fb = gid & 15;
    float acc[4];
#pragma unroll
    for (int c = 0; c < 4; c++) acc[c] = b3[fb + 16 * c] + nf[r * F + fb + 16 * c];
    const float* pr = g_P2 + r * H;
#pragma unroll 8
    for (int kk = 0; kk < H; kk++) {
        float x = fmaf(pr[kk], ss[kk], st[kk]);
        const float* w = W3 + kk * F + fb;
#pragma unroll
        for (int c = 0; c < 4; c++) acc[c] = fmaf(x, w[16 * c], acc[c]);
    }
#pragma unroll
    for (int c = 0; c < 4; c++) g_H3[r * F + fb + 16 * c] = acc[c];
}

// ---------------- edge stats fold ----------------
__global__ void k_estats(const float* __restrict__ g5, const float* __restrict__ be5,
                         const float* __restrict__ W6, const float* __restrict__ b6) {
    __shared__ float red[H];
    int k = threadIdx.x;
    double cnt = (double)E_EDGES;
    float m = (float)((double)g_acc[4 * H * 128 + k * 128] / cnt);
    float var = (float)((double)g_acc[5 * H * 128 + k * 128] / cnt) - m * m;
    float s = g5[k] / sqrtf(var + EPS);
    float t = be5[k] - m * s;
    float dw = W6[k * 2 + 1] - W6[k * 2 + 0];
    g_v[k] = s * dw;
    red[k] = t * dw;
    __syncthreads();
    for (int off = 64; off > 0; off >>= 1) {
        if (k < off) red[k] += red[k + off];
        __syncthreads();
    }
    if (k == 0) g_c0[0] = red[0] + (b6[1] - b6[0]);
}

// ---------------- edge kernel: tf32 mma.sync GEMM per (i, j-chunk) tile ----------------
// Tile 128(j) x 128(k), K=F=64. 8 warps: warp w -> (jw=w&1, kw=w>>1);
// warp tile 64(m) x 32(n): 4 m-tiles x 4 n-tiles of m16n8k8, 8 k-steps.
// smem (floats): sA 128x68, sB 64x132, sC(b5) 128, sV 128, scratch 512.
#define SA_STRIDE 68
#define SB_STRIDE 132
#define SM_FLOATS (128 * SA_STRIDE + 64 * SB_STRIDE + 128 + 128 + 512)
#define SM_BYTES (SM_FLOATS * 4)

template <int PASS>
__global__ void __launch_bounds__(256, 2)
k_edge(const float* __restrict__ W5, const float* __restrict__ b5,
       float* __restrict__ O) {
    int i = blockIdx.y;
    int j0 = blockIdx.x << 7;
    if (j0 + 127 <= i) return;

    extern __shared__ float sm[];
    float* sA = sm;                         // [128][68]  h_j rows (tf32)
    float* sB = sA + 128 * SA_STRIDE;       // [64][132]  diag(h_i)*W5 (tf32)
    float* sC = sB + 64 * SB_STRIDE;        // b5[128]
    float* sV = sC + 128;                   // v[128] (pass2)
    float* sS = sV + 128;                   // 128 col sums (pass1)
    float* sQ = sS + 128;                   // 128 col sumsq (pass1)
    float* sRow = sS;                       // [128][4] row partials (pass2)

    int tid = threadIdx.x;
    int wid = tid >> 5, lane = tid & 31;
    int g = lane >> 2, q = lane & 3;
    int jw = wid & 1, kw = wid >> 1;
    int m0 = jw * 64, n0 = kw * 32;

    if (tid < 128) {
        sC[tid] = b5[tid];
        if (PASS == 2) sV[tid] = g_v[tid];
        else { sS[tid] = 0.0f; sQ[tid] = 0.0f; }
    }

    const float* hi = g_H3 + (size_t)i * F;
    // fill A: h_j (zero rows for j<=i), tf32-rounded
#pragma unroll
    for (int it = 0; it < 8; it++) {
        int idx = tid + 256 * it;            // 2048 float4
        int j = idx >> 4, fq = (idx & 15) << 2;
        int jg = j0 + j;
        float4 v = (jg > i) ? *(const float4*)(g_H3 + (size_t)jg * F + fq)
                            : make_float4(0.f, 0.f, 0.f, 0.f);
        v.x = tf32r(v.x); v.y = tf32r(v.y); v.z = tf32r(v.z); v.w = tf32r(v.w);
        *(float4*)(sA + j * SA_STRIDE + fq) = v;
    }
    // fill B: row f = h_i[f] * W5[f][:], tf32-rounded
#pragma unroll
    for (int it = 0; it < 8; it++) {
        int idx = tid + 256 * it;            // 2048 float4
        int f = idx >> 5, kq = (idx & 31) << 2;
        float hv = hi[f];
        float4 w = *(const float4*)(W5 + f * H + kq);
        w.x = tf32r(w.x * hv); w.y = tf32r(w.y * hv);
        w.z = tf32r(w.z * hv); w.w = tf32r(w.w * hv);
        *(float4*)(sB + f * SB_STRIDE + kq) = w;
    }
    __syncthreads();

    float c[4][4][4];
#pragma unroll
    for (int mt = 0; mt < 4; mt++)
#pragma unroll
        for (int nt = 0; nt < 4; nt++)
#pragma unroll
            for (int e = 0; e < 4; e++) c[mt][nt][e] = 0.0f;

#pragma unroll
    for (int ks = 0; ks < 8; ks++) {
        int k0 = ks * 8;
        uint32_t a[4][4], b[4][2];
#pragma unroll
        for (int mt = 0; mt < 4; mt++) {
            const uint32_t* pa = (const uint32_t*)sA + (m0 + mt * 16 + g) * SA_STRIDE + k0 + q;
            a[mt][0] = pa[0];
            a[mt][1] = pa[8 * SA_STRIDE];
            a[mt][2] = pa[4];
            a[mt][3] = pa[8 * SA_STRIDE + 4];
        }
#pragma unroll
        for (int nt = 0; nt < 4; nt++) {
            const uint32_t* pb = (const uint32_t*)sB + (k0 + q) * SB_STRIDE + n0 + nt * 8 + g;
            b[nt][0] = pb[0];
            b[nt][1] = pb[4 * SB_STRIDE];
        }
#pragma unroll
        for (int mt = 0; mt < 4; mt++)
#pragma unroll
            for (int nt = 0; nt < 4; nt++)
                mma8(c[mt][nt], a[mt], b[nt]);
    }

    // ---- epilogue ----
    if (PASS == 1) {
        float ps[4][2], pq[4][2];
#pragma unroll
        for (int nt = 0; nt < 4; nt++)
            for (int e = 0; e < 2; e++) { ps[nt][e] = 0.0f; pq[nt][e] = 0.0f; }
#pragma unroll
        for (int mt = 0; mt < 4; mt++) {
            int r0 = j0 + m0 + mt * 16 + g;
            bool v0 = r0 > i, v1 = (r0 + 8) > i;
#pragma unroll
            for (int nt = 0; nt < 4; nt++) {
#pragma unroll
                for (int e = 0; e < 2; e++) {
                    int col = n0 + nt * 8 + 2 * q + e;
                    float bb = sC[col];
                    float z0 = c[mt][nt][e] + bb;
                    z0 = z0 > 0.0f ? z0 : NEG * z0;
                    if (!v0) z0 = 0.0f;
                    float z1 = c[mt][nt][2 + e] + bb;
                    z1 = z1 > 0.0f ? z1 : NEG * z1;
                    if (!v1) z1 = 0.0f;
                    ps[nt][e] += z0 + z1;
                    pq[nt][e] += z0 * z0 + z1 * z1;
                }
            }
        }
        // reduce over g (lanes differing in bits 2..4)
#pragma unroll
        for (int off = 4; off <= 16; off <<= 1) {
#pragma unroll
            for (int nt = 0; nt < 4; nt++)
#pragma unroll
                for (int e = 0; e < 2; e++) {
                    ps[nt][e] += __shfl_xor_sync(0xffffffffu, ps[nt][e], off);
                    pq[nt][e] += __shfl_xor_sync(0xffffffffu, pq[nt][e], off);
                }
        }
        if (g == 0) {
#pragma unroll
            for (int nt = 0; nt < 4; nt++)
#pragma unroll
                for (int e = 0; e < 2; e++) {
                    int col = n0 + nt * 8 + 2 * q + e;
                    atomicAdd(&sS[col], ps[nt][e]);
                    atomicAdd(&sQ[col], pq[nt][e]);
                }
        }
        __syncthreads();
        if (tid < 128) {
            atomicAdd(&g_acc[4 * H * 128 + tid * 128], sS[tid]);
            atomicAdd(&g_acc[5 * H * 128 + tid * 128], sQ[tid]);
        }
    } else {
        float rs[4][2];
#pragma unroll
        for (int mt = 0; mt < 4; mt++) { rs[mt][0] = 0.0f; rs[mt][1] = 0.0f; }
#pragma unroll
        for (int mt = 0; mt < 4; mt++) {
#pragma unroll
            for (int nt = 0; nt < 4; nt++) {
#pragma unroll
                for (int e = 0; e < 2; e++) {
                    int col = n0 + nt * 8 + 2 * q + e;
                    float bb = sC[col], vv = sV[col];
                    float z0 = c[mt][nt][e] + bb;
                    z0 = z0 > 0.0f ? z0 : NEG * z0;
                    float z1 = c[mt][nt][2 + e] + bb;
                    z1 = z1 > 0.0f ? z1 : NEG * z1;
                    rs[mt][0] = fmaf(z0, vv, rs[mt][0]);
                    rs[mt][1] = fmaf(z1, vv, rs[mt][1]);
                }
            }
        }
        // reduce over q (lanes differing in bits 0..1)
#pragma unroll
        for (int off = 1; off <= 2; off <<= 1) {
#pragma unroll
            for (int mt = 0; mt < 4; mt++) {
                rs[mt][0] += __shfl_xor_sync(0xffffffffu, rs[mt][0], off);
                rs[mt][1] += __shfl_xor_sync(0xffffffffu, rs[mt][1], off);
            }
        }
        if (q == 0) {
#pragma unroll
            for (int mt = 0; mt < 4; mt++) {
                int row = m0 + mt * 16 + g;
                sRow[row * 4 + kw] = rs[mt][0];
                sRow[(row + 8) * 4 + kw] = rs[mt][1];
            }
        }
        __syncthreads();
        if (tid < 128) {
            int jg = j0 + tid;
            if (jg > i) {
                float d = sRow[tid * 4] + sRow[tid * 4 + 1] +
                          sRow[tid * 4 + 2] + sRow[tid * 4 + 3] + g_c0[0];
                float p1 = 1.0f / (1.0f + expf(-d));
                float2 pr = make_float2(1.0f - p1, p1);
                float2* O2 = (float2*)O;
                O2[(size_t)i * N + jg] = pr;
                O2[(size_t)jg * N + i] = pr;
            }
        }
    }
}

// ---------------- launch ----------------
extern "C" void kernel_launch(void* const* d_in, const int* in_sizes, int n_in,
                              void* d_out, int out_size) {
    const float* nf  = (const float*)d_in[1];
    const float* W1  = (const float*)d_in[2];
    const float* b1  = (const float*)d_in[3];
    const float* g1  = (const float*)d_in[4];
    const float* be1 = (const float*)d_in[5];
    const float* W2  = (const float*)d_in[6];
    const float* b2  = (const float*)d_in[7];
    const float* g2  = (const float*)d_in[8];
    const float* be2 = (const float*)d_in[9];
    const float* W3  = (const float*)d_in[10];
    const float* b3  = (const float*)d_in[11];
    const float* W5  = (const float*)d_in[12];
    const float* b5  = (const float*)d_in[13];
    const float* g5  = (const float*)d_in[14];
    const float* be5 = (const float*)d_in[15];
    const float* W6  = (const float*)d_in[16];
    const float* b6  = (const float*)d_in[17];
    float* O = (float*)d_out;

    cudaFuncSetAttribute(k_edge<1>, cudaFuncAttributeMaxDynamicSharedMemorySize, SM_BYTES);
    cudaFuncSetAttribute(k_edge<2>, cudaFuncAttributeMaxDynamicSharedMemorySize, SM_BYTES);

    k_init<<<8, 256>>>(O);
    k_node1<<<N * H / 1024, 256>>>(nf, W1, b1);
    k_stats1<<<1, H>>>(g1, be1);
    k_node2<<<N * H / 1024, 256>>>(W2, b2);
    k_stats2<<<1, H>>>(g2, be2);
    k_node3<<<N * F / 1024, 256>>>(nf, W3, b3);

    dim3 egrid(N / 128, N);
    k_edge<1><<<egrid, 256, SM_BYTES>>>(W5, b5, O);
    k_estats<<<1, H>>>(g5, be5, W6, b6);
    k_edge<2><<<egrid, 256, SM_BYTES>>>(W5, b5, O);
}

// round 17
// speedup vs baseline: 2.5006x; 1.4556x over previous
#include <cuda_runtime.h>
#include <cuda_fp16.h>
#include <cstdint>
#include <math.h>

#define N 2048
#define F 64
#define H 128
#define C 2
#define NEG 0.01f
#define EPS 1e-5f
#define E_EDGES 2096128

// ---------------- scratch (static device globals) ----------------
__device__ float g_P1[N * H];
__device__ float g_P2[N * H];
__device__ __align__(16) float g_H3[N * F];
__device__ __align__(16) __half g_H3h[N * F];
__device__ __align__(16) float g_W5T[H * F];          // [k][f]
__device__ __align__(16) __half g_Bh[(size_t)N * H * F];  // [i][k][f] = h_i[f]*W5[f][k]
__device__ float g_acc[6 * H * 128];
__device__ float g_s1[H], g_t1[H], g_s2[H], g_t2[H];
__device__ __align__(16) float g_v[H];
__device__ float g_c0[1];

// ---------------- helpers ----------------
__device__ __forceinline__ void mma16(float* c, const uint32_t* a, const uint32_t* b) {
    asm volatile(
        "mma.sync.aligned.m16n8k16.row.col.f32.f16.f16.f32 "
        "{%0,%1,%2,%3}, {%4,%5,%6,%7}, {%8,%9}, {%0,%1,%2,%3};"
        : "+f"(c[0]), "+f"(c[1]), "+f"(c[2]), "+f"(c[3])
        : "r"(a[0]), "r"(a[1]), "r"(a[2]), "r"(a[3]), "r"(b[0]), "r"(b[1]));
}

// ---------------- init: zero accumulators + output diagonal ----------------
__global__ void k_init(float* __restrict__ O) {
    int t = blockIdx.x * 256 + threadIdx.x;
    if (t < 6 * H) g_acc[t * 128] = 0.0f;
    if (t < N) {
        size_t d = ((size_t)t * N + t) * C;
        O[d] = 0.0f;
        O[d + 1] = 0.0f;
    }
}
__global__ void k_prepW(const float* __restrict__ W5) {
    int t = blockIdx.x * 256 + threadIdx.x;   // F*H = 8192
    int f = t >> 7, k = t & 127;
    g_W5T[k * F + f] = W5[t];
}
// g_Bh[i][k][f] = H3[i][f] * W5T[k][f], fp16. thread handles 8 f (one uint4 out).
__global__ void k_prepB() {
    int t = blockIdx.x * 256 + threadIdx.x;   // N * H * 8 = 2.1M
    int i = t >> 10;
    int rem = t & 1023;
    int k = rem >> 3, f0 = (rem & 7) << 3;
    const float* hi = g_H3 + (size_t)i * F + f0;
    const float* wt = g_W5T + k * F + f0;
    float4 h0 = *(const float4*)hi;
    float4 h1 = *(const float4*)(hi + 4);
    float4 w0 = *(const float4*)wt;
    float4 w1 = *(const float4*)(wt + 4);
    __half2 o[4];
    o[0] = __floats2half2_rn(h0.x * w0.x, h0.y * w0.y);
    o[1] = __floats2half2_rn(h0.z * w0.z, h0.w * w0.w);
    o[2] = __floats2half2_rn(h1.x * w1.x, h1.y * w1.y);
    o[3] = __floats2half2_rn(h1.z * w1.z, h1.w * w1.w);
    *(uint4*)(g_Bh + (size_t)i * (H * F) + k * F + f0) = *(uint4*)o;
}

// ---------------- node layers: smem-tiled ----------------
__global__ void __launch_bounds__(256) k_node1(const float* __restrict__ nf,
                                               const float* __restrict__ W1,
                                               const float* __restrict__ b1) {
    __shared__ float sX[8 * 64];
    __shared__ float sS[128], sQ[128];
    int tid = threadIdx.x;
    int r0 = blockIdx.x * 8;
    if (tid < 128) { sS[tid] = 0.0f; sQ[tid] = 0.0f; }
    sX[tid] = nf[r0 * 64 + tid];
    sX[tid + 256] = nf[r0 * 64 + 256 + tid];
    __syncthreads();
    int r = tid >> 5, cg = tid & 31;
    float4 acc = *(const float4*)(b1 + 4 * cg);
    const float* xr = sX + r * 64;
#pragma unroll 8
    for (int f = 0; f < 64; f++) {
        float x = xr[f];
        float4 w = *(const float4*)(W1 + f * 128 + 4 * cg);
        acc.x = fmaf(x, w.x, acc.x); acc.y = fmaf(x, w.y, acc.y);
        acc.z = fmaf(x, w.z, acc.z); acc.w = fmaf(x, w.w, acc.w);
    }
    float z[4] = {acc.x, acc.y, acc.z, acc.w};
#pragma unroll
    for (int e = 0; e < 4; e++) {
        z[e] = z[e] > 0.0f ? z[e] : NEG * z[e];
        atomicAdd(&sS[4 * cg + e], z[e]);
        atomicAdd(&sQ[4 * cg + e], z[e] * z[e]);
    }
    *(float4*)(g_P1 + (r0 + r) * 128 + 4 * cg) = make_float4(z[0], z[1], z[2], z[3]);
    __syncthreads();
    if (tid < 128) {
        atomicAdd(&g_acc[0 * H * 128 + tid * 128], sS[tid]);
        atomicAdd(&g_acc[1 * H * 128 + tid * 128], sQ[tid]);
    }
}
__global__ void k_stats1(const float* __restrict__ g, const float* __restrict__ be) {
    int k = threadIdx.x;
    float m = g_acc[0 * H * 128 + k * 128] * (1.0f / N);
    float var = g_acc[1 * H * 128 + k * 128] * (1.0f / N) - m * m;
    float s = g[k] / sqrtf(var + EPS);
    g_s1[k] = s;
    g_t1[k] = be[k] - m * s;
}
__global__ void __launch_bounds__(256) k_node2(const float* __restrict__ W2,
                                               const float* __restrict__ b2) {
    __shared__ float sX[8 * 128];
    __shared__ float ss[128], st[128];
    __shared__ float sS[128], sQ[128];
    int tid = threadIdx.x;
    int r0 = blockIdx.x * 8;
    if (tid < 128) {
        ss[tid] = g_s1[tid]; st[tid] = g_t1[tid];
        sS[tid] = 0.0f; sQ[tid] = 0.0f;
    }
    __syncthreads();
#pragma unroll
    for (int u = 0; u < 4; u++) {
        int idx = tid + 256 * u;
        int col = idx & 127;
        sX[idx] = fmaf(g_P1[r0 * 128 + idx], ss[col], st[col]);
    }
    __syncthreads();
    int r = tid >> 5, cg = tid & 31;
    float4 acc = *(const float4*)(b2 + 4 * cg);
    const float* xr = sX + r * 128;
#pragma unroll 8
    for (int f = 0; f < 128; f++) {
        float x = xr[f];
        float4 w = *(const float4*)(W2 + f * 128 + 4 * cg);
        acc.x = fmaf(x, w.x, acc.x); acc.y = fmaf(x, w.y, acc.y);
        acc.z = fmaf(x, w.z, acc.z); acc.w = fmaf(x, w.w, acc.w);
    }
    float z[4] = {acc.x, acc.y, acc.z, acc.w};
#pragma unroll
    for (int e = 0; e < 4; e++) {
        z[e] = z[e] > 0.0f ? z[e] : NEG * z[e];
        atomicAdd(&sS[4 * cg + e], z[e]);
        atomicAdd(&sQ[4 * cg + e], z[e] * z[e]);
    }
    *(float4*)(g_P2 + (r0 + r) * 128 + 4 * cg) = make_float4(z[0], z[1], z[2], z[3]);
    __syncthreads();
    if (tid < 128) {
        atomicAdd(&g_acc[2 * H * 128 + tid * 128], sS[tid]);
        atomicAdd(&g_acc[3 * H * 128 + tid * 128], sQ[tid]);
    }
}
__global__ void k_stats2(const float* __restrict__ g, const float* __restrict__ be) {
    int k = threadIdx.x;
    float m = g_acc[2 * H * 128 + k * 128] * (1.0f / N);
    float var = g_acc[3 * H * 128 + k * 128] * (1.0f / N) - m * m;
    float s = g[k] / sqrtf(var + EPS);
    g_s2[k] = s;
    g_t2[k] = be[k] - m * s;
}
__global__ void __launch_bounds__(256) k_node3(const float* __restrict__ nf,
                                               const float* __restrict__ W3,
                                               const float* __restrict__ b3) {
    __shared__ float sX[16 * 128];
    __shared__ float ss[128], st[128];
    int tid = threadIdx.x;
    int r0 = blockIdx.x * 16;
    if (tid < 128) { ss[tid] = g_s2[tid]; st[tid] = g_t2[tid]; }
    __syncthreads();
#pragma unroll
    for (int u = 0; u < 8; u++) {
        int idx = tid + 256 * u;
        int col = idx & 127;
        sX[idx] = fmaf(g_P2[r0 * 128 + idx], ss[col], st[col]);
    }
    __syncthreads();
    int r = tid >> 4, cg = tid & 15;
    int row = r0 + r;
    float4 acc = *(const float4*)(b3 + 4 * cg);
    float4 xin = *(const float4*)(nf + row * 64 + 4 * cg);
    acc.x += xin.x; acc.y += xin.y; acc.z += xin.z; acc.w += xin.w;
    const float* xr = sX + r * 128;
#pragma unroll 8
    for (int kk = 0; kk < 128; kk++) {
        float x = xr[kk];
        float4 w = *(const float4*)(W3 + kk * 64 + 4 * cg);
        acc.x = fmaf(x, w.x, acc.x); acc.y = fmaf(x, w.y, acc.y);
        acc.z = fmaf(x, w.z, acc.z); acc.w = fmaf(x, w.w, acc.w);
    }
    *(float4*)(g_H3 + row * 64 + 4 * cg) = acc;
    __half2 h01 = __floats2half2_rn(acc.x, acc.y);
    __half2 h23 = __floats2half2_rn(acc.z, acc.w);
    *(__half2*)(g_H3h + row * 64 + 4 * cg) = h01;
    *(__half2*)(g_H3h + row * 64 + 4 * cg + 2) = h23;
}

// ---------------- edge stats fold ----------------
__global__ void k_estats(const float* __restrict__ g5, const float* __restrict__ be5,
                         const float* __restrict__ W6, const float* __restrict__ b6) {
    __shared__ float red[H];
    int k = threadIdx.x;
    double cnt = (double)E_EDGES;
    float m = (float)((double)g_acc[4 * H * 128 + k * 128] / cnt);
    float var = (float)((double)g_acc[5 * H * 128 + k * 128] / cnt) - m * m;
    float s = g5[k] / sqrtf(var + EPS);
    float t = be5[k] - m * s;
    float dw = W6[k * 2 + 1] - W6[k * 2 + 0];
    g_v[k] = s * dw;
    red[k] = t * dw;
    __syncthreads();
    for (int off = 64; off > 0; off >>= 1) {
        if (k < off) red[k] += red[k + off];
        __syncthreads();
    }
    if (k == 0) g_c0[0] = red[0] + (b6[1] - b6[0]);
}

// ---------------- edge kernel: fp16 m16n8k16 GEMM per (i, j-chunk) tile ----------------
// Tile 128(j) x 128(k_out), K=F=64 (4 k16 steps). 8 warps: (jw=wid&1, kw=wid>>1),
// warp tile 64m x 32n. sA/sB: 128 rows x 72 fp16 (b32 stride 36; banks 4g+q, conflict-free).
#define STRIDE32 36

template <int PASS>
__global__ void __launch_bounds__(256, 2)
k_edge(const float* __restrict__ b5, float* __restrict__ O) {
    int i = blockIdx.y;
    int j0 = blockIdx.x << 7;
    if (j0 + 127 <= i) return;

    __shared__ uint32_t sA[128 * STRIDE32];   // h_j tile fp16
    __shared__ uint32_t sB[128 * STRIDE32];   // Bh(i) tile fp16
    __shared__ float sB5[128], sV[128];
    __shared__ float sRed[512];               // pass1: sS/sQ ; pass2: sRow[128][4]
    float* sS = sRed;
    float* sQ = sRed + 128;
    float* sRow = sRed;

    int tid = threadIdx.x;
    int wid = tid >> 5, lane = tid & 31;
    int g = lane >> 2, q = lane & 3;
    int jw = wid & 1, kw = wid >> 1;
    int m0 = jw * 64, n0 = kw * 32;

    if (tid < 128) {
        sB5[tid] = b5[tid];
        if (PASS == 2) sV[tid] = g_v[tid];
        else { sS[tid] = 0.0f; sQ[tid] = 0.0f; }
    }

    // fill A (rows j, 64 fp16 each, zero for j<=i) and B (rows k_out)
    const uint4 zz = make_uint4(0u, 0u, 0u, 0u);
    const uint4* bsrc = (const uint4*)(g_Bh + (size_t)i * (H * F));
#pragma unroll
    for (int it = 0; it < 4; it++) {
        int idx = tid + 256 * it;            // 1024 uint4
        int row = idx >> 3, u = idx & 7;
        int jg = j0 + row;
        uint4 av = (jg > i) ? ((const uint4*)(g_H3h + (size_t)jg * F))[u] : zz;
        *(uint4*)((char*)sA + row * (STRIDE32 * 4) + u * 16) = av;
        *(uint4*)((char*)sB + row * (STRIDE32 * 4) + u * 16) = bsrc[idx];
    }
    __syncthreads();

    float c[4][4][4];
#pragma unroll
    for (int mt = 0; mt < 4; mt++)
#pragma unroll
        for (int nt = 0; nt < 4; nt++)
#pragma unroll
            for (int e = 0; e < 4; e++) c[mt][nt][e] = 0.0f;

#pragma unroll
    for (int ks = 0; ks < 4; ks++) {
        int k0 = ks * 8;
        uint32_t a[4][4], b[4][2];
#pragma unroll
        for (int mt = 0; mt < 4; mt++) {
            const uint32_t* pa = sA + (m0 + mt * 16 + g) * STRIDE32 + k0 + q;
            a[mt][0] = pa[0];
            a[mt][1] = pa[8 * STRIDE32];
            a[mt][2] = pa[4];
            a[mt][3] = pa[8 * STRIDE32 + 4];
        }
#pragma unroll
        for (int nt = 0; nt < 4; nt++) {
            const uint32_t* pb = sB + (n0 + nt * 8 + g) * STRIDE32 + k0 + q;
            b[nt][0] = pb[0];
            b[nt][1] = pb[4];
        }
#pragma unroll
        for (int mt = 0; mt < 4; mt++)
#pragma unroll
            for (int nt = 0; nt < 4; nt++)
                mma16(c[mt][nt], a[mt], b[nt]);
    }

    // ---- epilogue (c0,c1 = row g cols 2q,2q+1 ; c2,c3 = row g+8) ----
    if (PASS == 1) {
        float ps[4][2], pq[4][2];
#pragma unroll
        for (int nt = 0; nt < 4; nt++)
            for (int e = 0; e < 2; e++) { ps[nt][e] = 0.0f; pq[nt][e] = 0.0f; }
#pragma unroll
        for (int mt = 0; mt < 4; mt++) {
            int r0 = j0 + m0 + mt * 16 + g;
            bool v0 = r0 > i, v1 = (r0 + 8) > i;
#pragma unroll
            for (int nt = 0; nt < 4; nt++) {
#pragma unroll
                for (int e = 0; e < 2; e++) {
                    int col = n0 + nt * 8 + 2 * q + e;
                    float bb = sB5[col];
                    float z0 = c[mt][nt][e] + bb;
                    z0 = z0 > 0.0f ? z0 : NEG * z0;
                    if (!v0) z0 = 0.0f;
                    float z1 = c[mt][nt][2 + e] + bb;
                    z1 = z1 > 0.0f ? z1 : NEG * z1;
                    if (!v1) z1 = 0.0f;
                    ps[nt][e] += z0 + z1;
                    pq[nt][e] += z0 * z0 + z1 * z1;
                }
            }
        }
#pragma unroll
        for (int off = 4; off <= 16; off <<= 1) {
#pragma unroll
            for (int nt = 0; nt < 4; nt++)
#pragma unroll
                for (int e = 0; e < 2; e++) {
                    ps[nt][e] += __shfl_xor_sync(0xffffffffu, ps[nt][e], off);
                    pq[nt][e] += __shfl_xor_sync(0xffffffffu, pq[nt][e], off);
                }
        }
        if (g == 0) {
#pragma unroll
            for (int nt = 0; nt < 4; nt++)
#pragma unroll
                for (int e = 0; e < 2; e++) {
                    int col = n0 + nt * 8 + 2 * q + e;
                    atomicAdd(&sS[col], ps[nt][e]);
                    atomicAdd(&sQ[col], pq[nt][e]);
                }
        }
        __syncthreads();
        if (tid < 128) {
            atomicAdd(&g_acc[4 * H * 128 + tid * 128], sS[tid]);
            atomicAdd(&g_acc[5 * H * 128 + tid * 128], sQ[tid]);
        }
    } else {
        float rs[4][2];
#pragma unroll
        for (int mt = 0; mt < 4; mt++) { rs[mt][0] = 0.0f; rs[mt][1] = 0.0f; }
#pragma unroll
        for (int mt = 0; mt < 4; mt++) {
#pragma unroll
            for (int nt = 0; nt < 4; nt++) {
#pragma unroll
                for (int e = 0; e < 2; e++) {
                    int col = n0 + nt * 8 + 2 * q + e;
                    float bb = sB5[col], vv = sV[col];
                    float z0 = c[mt][nt][e] + bb;
                    z0 = z0 > 0.0f ? z0 : NEG * z0;
                    float z1 = c[mt][nt][2 + e] + bb;
                    z1 = z1 > 0.0f ? z1 : NEG * z1;
                    rs[mt][0] = fmaf(z0, vv, rs[mt][0]);
                    rs[mt][1] = fmaf(z1, vv, rs[mt][1]);
                }
            }
        }
#pragma unroll
        for (int off = 1; off <= 2; off <<= 1) {
#pragma unroll
            for (int mt = 0; mt < 4; mt++) {
                rs[mt][0] += __shfl_xor_sync(0xffffffffu, rs[mt][0], off);
                rs[mt][1] += __shfl_xor_sync(0xffffffffu, rs[mt][1], off);
            }
        }
        if (q == 0) {
#pragma unroll
            for (int mt = 0; mt < 4; mt++) {
                int row = m0 + mt * 16 + g;
                sRow[row * 4 + kw] = rs[mt][0];
                sRow[(row + 8) * 4 + kw] = rs[mt][1];
            }
        }
        __syncthreads();
        if (tid < 128) {
            int jg = j0 + tid;
            if (jg > i) {
                float d = sRow[tid * 4] + sRow[tid * 4 + 1] +
                          sRow[tid * 4 + 2] + sRow[tid * 4 + 3] + g_c0[0];
                float p1 = 1.0f / (1.0f + expf(-d));
                float2 pr = make_float2(1.0f - p1, p1);
                float2* O2 = (float2*)O;
                O2[(size_t)i * N + jg] = pr;
                O2[(size_t)jg * N + i] = pr;
            }
        }
    }
}

// ---------------- launch ----------------
extern "C" void kernel_launch(void* const* d_in, const int* in_sizes, int n_in,
                              void* d_out, int out_size) {
    const float* nf  = (const float*)d_in[1];
    const float* W1  = (const float*)d_in[2];
    const float* b1  = (const float*)d_in[3];
    const float* g1  = (const float*)d_in[4];
    const float* be1 = (const float*)d_in[5];
    const float* W2  = (const float*)d_in[6];
    const float* b2  = (const float*)d_in[7];
    const float* g2  = (const float*)d_in[8];
    const float* be2 = (const float*)d_in[9];
    const float* W3  = (const float*)d_in[10];
    const float* b3  = (const float*)d_in[11];
    const float* W5  = (const float*)d_in[12];
    const float* b5  = (const float*)d_in[13];
    const float* g5  = (const float*)d_in[14];
    const float* be5 = (const float*)d_in[15];
    const float* W6  = (const float*)d_in[16];
    const float* b6  = (const float*)d_in[17];
    float* O = (float*)d_out;

    k_init<<<8, 256>>>(O);
    k_prepW<<<F * H / 256, 256>>>(W5);
    k_node1<<<N / 8, 256>>>(nf, W1, b1);
    k_stats1<<<1, H>>>(g1, be1);
    k_node2<<<N / 8, 256>>>(W2, b2);
    k_stats2<<<1, H>>>(g2, be2);
    k_node3<<<N / 16, 256>>>(nf, W3, b3);
    k_prepB<<<N * H * 8 / 256, 256>>>();

    dim3 egrid(N / 128, N);
    k_edge<1><<<egrid, 256>>>(b5, O);
    k_estats<<<1, H>>>(g5, be5, W6, b6);
    k_edge<2><<<egrid, 256>>>(b5, O);
}